// round 1
// baseline (speedup 1.0000x reference)
#include <cuda_runtime.h>
#include <cuda_bf16.h>
#include <stdint.h>

#define B_DIM 32
#define S_DIM 2048
#define MD 128
#define LB 64
#define NW 2041          // S - RANK + 1
#define NCHUNK 16
#define WTILE 128
#define NTILES (B_DIM * NCHUNK)   // 512
#define GRID1 256
#define TILES_PER_BLOCK (NTILES / GRID1)  // 2

// Scratch (device globals: no allocations allowed)
__device__ float g_part[GRID1 * MD * MD];   // per-block partial Gram (16 MB)
__device__ float g_C64[LB * MD];            // C[w%64][m] = sum_n M[n][m]*Nk[l][n]
__device__ float g_G[MD * MD];              // G[m][m'] = sum_n M[n][m]*M[n][m']
__device__ float g_rowdot[MD];
__device__ float g_crossPart[GRID1];
__device__ float g_nksq[LB];

// ---------------- K0: Nk-derived tables -------------------
__global__ void k_prep(const float* __restrict__ M,
                       const float* __restrict__ A,
                       const float* __restrict__ Bb) {
    int l = blockIdx.x;          // 0..63
    int t = threadIdx.x;         // 0..127  (n or m)
    __shared__ float nk[MD];
    __shared__ float red[MD];
    float v = A[t * LB + l] * Bb[l * MD + t];   // Nk[l][n=t]
    nk[t] = v;
    red[t] = v * v;
    __syncthreads();
    float c = 0.f;
#pragma unroll 8
    for (int n = 0; n < MD; n++) c += M[n * MD + t] * nk[n];
    g_C64[l * MD + t] = c;
    for (int s = 64; s > 0; s >>= 1) {
        if (t < s) red[t] += red[t + s];
        __syncthreads();
    }
    if (t == 0) g_nksq[l] = red[0];
}

// ---------------- KG: G = M^T M ----------------------------
__global__ void k_gram_m(const float* __restrict__ M) {
    int m = blockIdx.x, mp = threadIdx.x;
    float s = 0.f;
#pragma unroll 8
    for (int n = 0; n < MD; n++) s += M[n * MD + m] * M[n * MD + mp];
    g_G[m * MD + mp] = s;
}

// ---------------- K1: main fused kernel --------------------
// Per tile (b, chunk): compute agg (sliding mean), cross term (fp32),
// store agg^T as bf16 in SMEM, accumulate Gram via mma.sync bf16.
__global__ void __launch_bounds__(256, 2) k_main(const float* __restrict__ seq) {
    __shared__ uint32_t At[MD][68];   // 128 rows x 136 bf16 (pad 8 -> conflict-free)
    __shared__ float sred[256];

    int tid  = threadIdx.x;
    int lane = tid & 31;
    int wid  = tid >> 5;

    float acc[2][8][4];
#pragma unroll
    for (int a = 0; a < 2; a++)
#pragma unroll
        for (int b = 0; b < 8; b++)
#pragma unroll
            for (int c = 0; c < 4; c++) acc[a][b][c] = 0.f;

    float cross = 0.f;

#pragma unroll 1
    for (int it = 0; it < TILES_PER_BLOCK; it++) {
        int tile  = blockIdx.x + GRID1 * it;
        int b     = tile >> 4;
        int chunk = tile & 15;
        int w0    = chunk * WTILE;
        int wt    = min(WTILE, NW - w0);

        // ---- phase 1: sliding-window agg + bf16 transpose store + cross ----
        {
            int m    = tid & 127;
            int wseg = tid >> 7;          // 0 or 1
            int wb   = wseg * 64;
            int srow0 = w0 + wb;
            const float* sp = seq + ((size_t)b * S_DIM + srow0) * MD + m;
            float s = 0.f;
#pragma unroll
            for (int i = 0; i < 7; i++) s += sp[i * MD];
#pragma unroll 8
            for (int w = 0; w < 64; w += 2) {
                int r1 = srow0 + w + 7;
                float x1 = (r1 < S_DIM) ? sp[(w + 7) * MD] : 0.f;
                s += x1;
                float a0 = (wb + w < wt) ? s * 0.125f : 0.f;
                cross += a0 * g_C64[w * MD + m];        // (w0+wb+w)%64 == w
                s -= sp[w * MD];

                int r2 = r1 + 1;
                float x2 = (r2 < S_DIM) ? sp[(w + 8) * MD] : 0.f;
                s += x2;
                float a1 = (wb + w + 1 < wt) ? s * 0.125f : 0.f;
                cross += a1 * g_C64[(w + 1) * MD + m];
                s -= sp[(w + 1) * MD];

                __nv_bfloat162 pk = __floats2bfloat162_rn(a0, a1); // low = even k
                At[m][(wb + w) >> 1] = *reinterpret_cast<uint32_t*>(&pk);
            }
        }
        __syncthreads();

        // ---- phase 2: Gram += At * At^T  (mma.sync m16n8k16 bf16) ----
        {
            int wm = (wid & 3) << 5;   // m offset (4 warps along M)
            int wn = (wid >> 2) << 6;  // n offset (2 warps along N)
            int g  = lane >> 2;
            int tc = lane & 3;
#pragma unroll
            for (int ks = 0; ks < 8; ks++) {
                int kc = ks * 8 + tc;  // u32 column index (k/2)
                uint32_t af[2][4], bf[8][2];
#pragma unroll
                for (int mt = 0; mt < 2; mt++) {
                    int r = wm + mt * 16 + g;
                    af[mt][0] = At[r][kc];
                    af[mt][1] = At[r + 8][kc];
                    af[mt][2] = At[r][kc + 4];
                    af[mt][3] = At[r + 8][kc + 4];
                }
#pragma unroll
                for (int nt = 0; nt < 8; nt++) {
                    int r = wn + nt * 8 + g;
                    bf[nt][0] = At[r][kc];
                    bf[nt][1] = At[r][kc + 4];
                }
#pragma unroll
                for (int nt = 0; nt < 8; nt++)
#pragma unroll
                    for (int mt = 0; mt < 2; mt++)
                        asm volatile(
                            "mma.sync.aligned.m16n8k16.row.col.f32.bf16.bf16.f32 "
                            "{%0,%1,%2,%3}, {%4,%5,%6,%7}, {%8,%9}, {%0,%1,%2,%3};"
                            : "+f"(acc[mt][nt][0]), "+f"(acc[mt][nt][1]),
                              "+f"(acc[mt][nt][2]), "+f"(acc[mt][nt][3])
                            : "r"(af[mt][0]), "r"(af[mt][1]),
                              "r"(af[mt][2]), "r"(af[mt][3]),
                              "r"(bf[nt][0]), "r"(bf[nt][1]));
            }
        }
        __syncthreads();
    }

    // ---- write per-block partial Gram ----
    {
        int wm = (wid & 3) << 5;
        int wn = (wid >> 2) << 6;
        int g  = lane >> 2;
        int tc = lane & 3;
        float* base = g_part + (size_t)blockIdx.x * MD * MD;
#pragma unroll
        for (int mt = 0; mt < 2; mt++)
#pragma unroll
            for (int nt = 0; nt < 8; nt++) {
                int r = wm + mt * 16 + g;
                int c = wn + nt * 8 + 2 * tc;
                float2 v0 = make_float2(acc[mt][nt][0], acc[mt][nt][1]);
                float2 v1 = make_float2(acc[mt][nt][2], acc[mt][nt][3]);
                *reinterpret_cast<float2*>(base + (size_t)r * MD + c) = v0;
                *reinterpret_cast<float2*>(base + (size_t)(r + 8) * MD + c) = v1;
            }
    }

    // ---- block-reduce cross term (deterministic: one slot per block) ----
    sred[tid] = cross;
    __syncthreads();
    for (int s = 128; s > 0; s >>= 1) {
        if (tid < s) sred[tid] += sred[tid + s];
        __syncthreads();
    }
    if (tid == 0) g_crossPart[blockIdx.x] = sred[0];
}

// ---------------- KR: reduce partial Grams, dot with G ------
__global__ void k_reduce() {
    int m = blockIdx.x;
    int tid = threadIdx.x;
    int n = tid & 127;
    int half = tid >> 7;
    float s = 0.f;
    const float* p = g_part + (size_t)(half * 128) * MD * MD + m * MD + n;
#pragma unroll 4
    for (int i = 0; i < 128; i++) s += p[(size_t)i * MD * MD];
    __shared__ float sh[256];
    sh[tid] = s;
    __syncthreads();
    if (tid < 128) sh[tid] = (sh[tid] + sh[tid + 128]) * g_G[m * MD + tid];
    __syncthreads();
    for (int st = 64; st > 0; st >>= 1) {
        if (tid < st) sh[tid] += sh[tid + st];
        __syncthreads();
    }
    if (tid == 0) g_rowdot[m] = sh[0];
}

// ---------------- KF: final scalar --------------------------
__global__ void k_final(float* __restrict__ out) {
    __shared__ float sh[256];
    int t = threadIdx.x;
    float dot = (t < MD) ? g_rowdot[t] : 0.f;
    float cr  = g_crossPart[t];
    float nk  = 0.f;
    if (t < LB) {
        int cnt = (NW - 1 - t) / 64 + 1;   // #windows with w%64 == t
        nk = (float)cnt * g_nksq[t];
    }
    sh[t] = dot - 2.f * cr + (float)B_DIM * nk;
    __syncthreads();
    for (int st = 128; st > 0; st >>= 1) {
        if (t < st) sh[t] += sh[t + st];
        __syncthreads();
    }
    if (t == 0) out[0] = sh[0] / ((float)B_DIM * (float)NW * (float)MD);
}

extern "C" void kernel_launch(void* const* d_in, const int* in_sizes, int n_in,
                              void* d_out, int out_size) {
    (void)in_sizes; (void)n_in; (void)out_size;
    const float* seq = (const float*)d_in[0];
    const float* M   = (const float*)d_in[1];
    const float* A   = (const float*)d_in[2];
    const float* Bb  = (const float*)d_in[3];
    float* out = (float*)d_out;

    k_prep<<<LB, MD>>>(M, A, Bb);
    k_gram_m<<<MD, MD>>>(M);
    k_main<<<GRID1, 256>>>(seq);
    k_reduce<<<MD, 256>>>();
    k_final<<<1, 256>>>(out);
}

// round 2
// speedup vs baseline: 1.0355x; 1.0355x over previous
#include <cuda_runtime.h>
#include <cuda_bf16.h>
#include <stdint.h>

#define B_DIM 32
#define S_DIM 2048
#define MD 128
#define LB 64
#define NW 2041          // S - RANK + 1
#define NCHUNK 16
#define WTILE 128
#define NTILES (B_DIM * NCHUNK)   // 512

// Scratch (device globals: no allocations allowed)
__device__ float g_C64[LB * MD];            // C[w%64][m] = sum_n M[n][m]*Nk[l][n]
__device__ float g_G[MD * MD];              // G[m][m'] = sum_n M[n][m]*M[n][m']
__device__ float g_dotPart[NTILES];
__device__ float g_crossPart[NTILES];
__device__ float g_nksq[LB];

// ---------------- K0: Nk-derived tables -------------------
__global__ void k_prep(const float* __restrict__ M,
                       const float* __restrict__ A,
                       const float* __restrict__ Bb) {
    int l = blockIdx.x;          // 0..63
    int t = threadIdx.x;         // 0..127  (n or m)
    __shared__ float nk[MD];
    __shared__ float red[MD];
    float v = A[t * LB + l] * Bb[l * MD + t];   // Nk[l][n=t]
    nk[t] = v;
    red[t] = v * v;
    __syncthreads();
    float c = 0.f;
#pragma unroll 8
    for (int n = 0; n < MD; n++) c += M[n * MD + t] * nk[n];
    g_C64[l * MD + t] = c;
    for (int s = 64; s > 0; s >>= 1) {
        if (t < s) red[t] += red[t + s];
        __syncthreads();
    }
    if (t == 0) g_nksq[l] = red[0];
}

// ---------------- KG: G = M^T M ----------------------------
__global__ void k_gram_m(const float* __restrict__ M) {
    int m = blockIdx.x, mp = threadIdx.x;
    float s = 0.f;
#pragma unroll 8
    for (int n = 0; n < MD; n++) s += M[n * MD + m] * M[n * MD + mp];
    g_G[m * MD + mp] = s;
}

// ---------------- K1: main fused kernel --------------------
// Per tile (b, chunk): compute agg (sliding mean), cross term (fp32),
// store agg^T as bf16 in SMEM, accumulate Gram via mma.sync bf16,
// then dot the register-resident partial Gram with G -> one float.
__global__ void __launch_bounds__(256) k_main(const float* __restrict__ seq) {
    __shared__ uint32_t At[MD][68];   // 128 rows x 136 bf16 (pad 8 -> conflict-free)
    __shared__ float sred[256];
    __shared__ float sred2[256];

    int tid  = threadIdx.x;
    int lane = tid & 31;
    int wid  = tid >> 5;

    float acc[2][8][4];
#pragma unroll
    for (int a = 0; a < 2; a++)
#pragma unroll
        for (int b = 0; b < 8; b++)
#pragma unroll
            for (int c = 0; c < 4; c++) acc[a][b][c] = 0.f;

    float cross = 0.f;

    int tile  = blockIdx.x;
    int b     = tile >> 4;
    int chunk = tile & 15;
    int w0    = chunk * WTILE;
    int wt    = min(WTILE, NW - w0);

    // ---- phase 1: sliding-window agg + bf16 transpose store + cross ----
    {
        int m    = tid & 127;
        int wseg = tid >> 7;          // 0 or 1
        int wb   = wseg * 64;
        int srow0 = w0 + wb;
        const float* sp = seq + ((size_t)b * S_DIM + srow0) * MD + m;
        float s = 0.f;
#pragma unroll
        for (int i = 0; i < 7; i++) s += sp[i * MD];
#pragma unroll 8
        for (int w = 0; w < 64; w += 2) {
            int r1 = srow0 + w + 7;
            float x1 = (r1 < S_DIM) ? sp[(w + 7) * MD] : 0.f;
            s += x1;
            float a0 = (wb + w < wt) ? s * 0.125f : 0.f;
            cross += a0 * __ldg(&g_C64[w * MD + m]);   // (w0+wb+w)%64 == w
            s -= sp[w * MD];

            int r2 = r1 + 1;
            float x2 = (r2 < S_DIM) ? sp[(w + 8) * MD] : 0.f;
            s += x2;
            float a1 = (wb + w + 1 < wt) ? s * 0.125f : 0.f;
            cross += a1 * __ldg(&g_C64[(w + 1) * MD + m]);
            s -= sp[(w + 1) * MD];

            __nv_bfloat162 pk = __floats2bfloat162_rn(a0, a1); // low = even k
            At[m][(wb + w) >> 1] = *reinterpret_cast<uint32_t*>(&pk);
        }
    }
    __syncthreads();

    // ---- phase 2: Gram += At * At^T  (mma.sync m16n8k16 bf16) ----
    int wm = (wid & 3) << 5;   // m offset (4 warps along M)
    int wn = (wid >> 2) << 6;  // n offset (2 warps along N)
    int g  = lane >> 2;
    int tc = lane & 3;
    {
#pragma unroll
        for (int ks = 0; ks < 8; ks++) {
            int kc = ks * 8 + tc;  // u32 column index (k/2)
            uint32_t af[2][4], bf[8][2];
#pragma unroll
            for (int mt = 0; mt < 2; mt++) {
                int r = wm + mt * 16 + g;
                af[mt][0] = At[r][kc];
                af[mt][1] = At[r + 8][kc];
                af[mt][2] = At[r][kc + 4];
                af[mt][3] = At[r + 8][kc + 4];
            }
#pragma unroll
            for (int nt = 0; nt < 8; nt++) {
                int r = wn + nt * 8 + g;
                bf[nt][0] = At[r][kc];
                bf[nt][1] = At[r][kc + 4];
            }
#pragma unroll
            for (int nt = 0; nt < 8; nt++)
#pragma unroll
                for (int mt = 0; mt < 2; mt++)
                    asm volatile(
                        "mma.sync.aligned.m16n8k16.row.col.f32.bf16.bf16.f32 "
                        "{%0,%1,%2,%3}, {%4,%5,%6,%7}, {%8,%9}, {%0,%1,%2,%3};"
                        : "+f"(acc[mt][nt][0]), "+f"(acc[mt][nt][1]),
                          "+f"(acc[mt][nt][2]), "+f"(acc[mt][nt][3])
                        : "r"(af[mt][0]), "r"(af[mt][1]),
                          "r"(af[mt][2]), "r"(af[mt][3]),
                          "r"(bf[nt][0]), "r"(bf[nt][1]));
        }
    }

    // ---- epilogue: dot partial Gram (in registers) with G ----
    float dot = 0.f;
#pragma unroll
    for (int mt = 0; mt < 2; mt++)
#pragma unroll
        for (int nt = 0; nt < 8; nt++) {
            int r = wm + mt * 16 + g;
            int c = wn + nt * 8 + 2 * tc;
            dot += acc[mt][nt][0] * __ldg(&g_G[r * MD + c]);
            dot += acc[mt][nt][1] * __ldg(&g_G[r * MD + c + 1]);
            dot += acc[mt][nt][2] * __ldg(&g_G[(r + 8) * MD + c]);
            dot += acc[mt][nt][3] * __ldg(&g_G[(r + 8) * MD + c + 1]);
        }

    // ---- block-reduce cross + dot (deterministic: one slot per block) ----
    sred[tid]  = cross;
    sred2[tid] = dot;
    __syncthreads();
    for (int s = 128; s > 0; s >>= 1) {
        if (tid < s) { sred[tid] += sred[tid + s]; sred2[tid] += sred2[tid + s]; }
        __syncthreads();
    }
    if (tid == 0) {
        g_crossPart[blockIdx.x] = sred[0];
        g_dotPart[blockIdx.x]   = sred2[0];
    }
}

// ---------------- KF: final scalar --------------------------
__global__ void k_final(float* __restrict__ out) {
    __shared__ float sh[NTILES];
    int t = threadIdx.x;
    float v = g_dotPart[t] - 2.f * g_crossPart[t];
    if (t < LB) {
        int cnt = (NW - 1 - t) / 64 + 1;   // #windows with w%64 == t
        v += (float)B_DIM * (float)cnt * g_nksq[t];
    }
    sh[t] = v;
    __syncthreads();
    for (int st = NTILES / 2; st > 0; st >>= 1) {
        if (t < st) sh[t] += sh[t + st];
        __syncthreads();
    }
    if (t == 0) out[0] = sh[0] / ((float)B_DIM * (float)NW * (float)MD);
}

extern "C" void kernel_launch(void* const* d_in, const int* in_sizes, int n_in,
                              void* d_out, int out_size) {
    (void)in_sizes; (void)n_in; (void)out_size;
    const float* seq = (const float*)d_in[0];
    const float* M   = (const float*)d_in[1];
    const float* A   = (const float*)d_in[2];
    const float* Bb  = (const float*)d_in[3];
    float* out = (float*)d_out;

    k_prep<<<LB, MD>>>(M, A, Bb);
    k_gram_m<<<MD, MD>>>(M);
    k_main<<<NTILES, 256>>>(seq);
    k_final<<<1, NTILES>>>(out);
}

// round 3
// speedup vs baseline: 1.4094x; 1.3611x over previous
#include <cuda_runtime.h>
#include <cuda_bf16.h>
#include <stdint.h>

#define B_DIM 32
#define S_DIM 2048
#define MD 128
#define LB 64
#define NW 2041          // S - RANK + 1
#define WTILE 128
#define NTILES 512       // 32 batches x 16 chunks

// Scratch (device globals: no allocations allowed)
__device__ float g_C64[LB * MD];   // C[w%64][m] = sum_n M[n][m]*Nk[l][n]
__device__ float g_G[MD * MD];     // G[m][m'] = sum_n M[n][m]*M[n][m']
__device__ float g_nksq[LB];
__device__ float g_part[NTILES];
__device__ unsigned int g_count;   // zero-init; reset by last block each call

// ---------------- K1: setup (prep + gram merged) -------------------
__global__ void k_setup(const float* __restrict__ M,
                        const float* __restrict__ A,
                        const float* __restrict__ Bb) {
    int t = threadIdx.x;   // 0..127
    if (blockIdx.x < LB) {
        int l = blockIdx.x;                 // 0..63
        __shared__ float nk[MD];
        __shared__ float red[MD];
        float v = A[t * LB + l] * Bb[l * MD + t];   // Nk[l][n=t]
        nk[t] = v;
        red[t] = v * v;
        __syncthreads();
        float c = 0.f;
#pragma unroll 8
        for (int n = 0; n < MD; n++) c += M[n * MD + t] * nk[n];
        g_C64[l * MD + t] = c;
        for (int s = 64; s > 0; s >>= 1) {
            if (t < s) red[t] += red[t + s];
            __syncthreads();
        }
        if (t == 0) g_nksq[l] = red[0];
    } else {
        int m = blockIdx.x - LB;            // 0..127
        float s = 0.f;
#pragma unroll 8
        for (int n = 0; n < MD; n++) s += M[n * MD + m] * M[n * MD + t];
        g_G[m * MD + t] = s;
    }
}

// ---------------- K2: main fused kernel --------------------
__global__ void __launch_bounds__(256, 2) k_main(const float* __restrict__ seq,
                                                 float* __restrict__ out) {
    __shared__ uint32_t At[MD][68];   // 128 rows x 136 bf16 (pad -> conflict-free)
    __shared__ float sred[256];
    __shared__ unsigned int s_ticket;

    int tid  = threadIdx.x;
    int lane = tid & 31;
    int wid  = tid >> 5;

    float acc[2][8][4];
#pragma unroll
    for (int a = 0; a < 2; a++)
#pragma unroll
        for (int b = 0; b < 8; b++)
#pragma unroll
            for (int c = 0; c < 4; c++) acc[a][b][c] = 0.f;

    float cross = 0.f;

    int tile  = blockIdx.x;
    int b     = tile >> 4;
    int chunk = tile & 15;
    int w0    = chunk * WTILE;
    int wt    = min(WTILE, NW - w0);

    // ---- phase 1: sliding-window agg (8-deep ring) + bf16 transpose + cross ----
    {
        int m    = tid & 127;
        int wseg = tid >> 7;          // 0 or 1
        int wb   = wseg * 64;
        int srow0 = w0 + wb;
        const float* sp = seq + ((size_t)b * S_DIM + srow0) * MD + m;

        float v[8];
        float s = 0.f;
#pragma unroll
        for (int i = 0; i < 7; i++) { v[i] = sp[i * MD]; s += v[i]; }

#pragma unroll
        for (int w = 0; w < 64; w += 2) {
            float x0 = (srow0 + w + 7 < S_DIM) ? sp[(w + 7) * MD] : 0.f;
            v[(w + 7) & 7] = x0;
            s += x0;
            float a0 = (wb + w < wt) ? s * 0.125f : 0.f;
            cross += a0 * __ldg(&g_C64[w * MD + m]);   // (w0+wb+w)%64 == w
            s -= v[w & 7];

            float x1 = (srow0 + w + 8 < S_DIM) ? sp[(w + 8) * MD] : 0.f;
            v[(w + 8) & 7] = x1;
            s += x1;
            float a1 = (wb + w + 1 < wt) ? s * 0.125f : 0.f;
            cross += a1 * __ldg(&g_C64[(w + 1) * MD + m]);
            s -= v[(w + 1) & 7];

            __nv_bfloat162 pk = __floats2bfloat162_rn(a0, a1); // low = even k
            At[m][(wb + w) >> 1] = *reinterpret_cast<uint32_t*>(&pk);
        }
    }
    __syncthreads();

    // ---- phase 2: Gram += At * At^T  (mma.sync m16n8k16 bf16) ----
    int wm = (wid & 3) << 5;   // m offset (4 warps along M)
    int wn = (wid >> 2) << 6;  // n offset (2 warps along N)
    int g  = lane >> 2;
    int tc = lane & 3;
#pragma unroll
    for (int ks = 0; ks < 8; ks++) {
        int kc = ks * 8 + tc;  // u32 column index (k/2)
        uint32_t af[2][4], bf[8][2];
#pragma unroll
        for (int mt = 0; mt < 2; mt++) {
            int r = wm + mt * 16 + g;
            af[mt][0] = At[r][kc];
            af[mt][1] = At[r + 8][kc];
            af[mt][2] = At[r][kc + 4];
            af[mt][3] = At[r + 8][kc + 4];
        }
#pragma unroll
        for (int nt = 0; nt < 8; nt++) {
            int r = wn + nt * 8 + g;
            bf[nt][0] = At[r][kc];
            bf[nt][1] = At[r][kc + 4];
        }
#pragma unroll
        for (int nt = 0; nt < 8; nt++)
#pragma unroll
            for (int mt = 0; mt < 2; mt++)
                asm volatile(
                    "mma.sync.aligned.m16n8k16.row.col.f32.bf16.bf16.f32 "
                    "{%0,%1,%2,%3}, {%4,%5,%6,%7}, {%8,%9}, {%0,%1,%2,%3};"
                    : "+f"(acc[mt][nt][0]), "+f"(acc[mt][nt][1]),
                      "+f"(acc[mt][nt][2]), "+f"(acc[mt][nt][3])
                    : "r"(af[mt][0]), "r"(af[mt][1]),
                      "r"(af[mt][2]), "r"(af[mt][3]),
                      "r"(bf[nt][0]), "r"(bf[nt][1]));
    }

    // ---- epilogue: dot partial Gram (registers) with G ----
    float dot = 0.f;
#pragma unroll
    for (int mt = 0; mt < 2; mt++)
#pragma unroll
        for (int nt = 0; nt < 8; nt++) {
            int r = wm + mt * 16 + g;
            int c = wn + nt * 8 + 2 * tc;
            dot += acc[mt][nt][0] * __ldg(&g_G[r * MD + c]);
            dot += acc[mt][nt][1] * __ldg(&g_G[r * MD + c + 1]);
            dot += acc[mt][nt][2] * __ldg(&g_G[(r + 8) * MD + c]);
            dot += acc[mt][nt][3] * __ldg(&g_G[(r + 8) * MD + c + 1]);
        }

    // ---- block reduce (dot - 2*cross) ----
    sred[tid] = dot - 2.f * cross;
    __syncthreads();
    for (int s = 128; s > 0; s >>= 1) {
        if (tid < s) sred[tid] += sred[tid + s];
        __syncthreads();
    }

    // ---- last-block final reduction (replay-safe ticket) ----
    if (tid == 0) {
        g_part[blockIdx.x] = sred[0];
        __threadfence();
        s_ticket = atomicAdd(&g_count, 1u);
    }
    __syncthreads();
    if (s_ticket == NTILES - 1) {
        float v = g_part[tid] + g_part[tid + 256];
        if (tid < LB) {
            int cnt = (NW - 1 - tid) / 64 + 1;   // #windows with w%64 == tid
            v += (float)B_DIM * (float)cnt * g_nksq[tid];
        }
        sred[tid] = v;
        __syncthreads();
        for (int s = 128; s > 0; s >>= 1) {
            if (tid < s) sred[tid] += sred[tid + s];
            __syncthreads();
        }
        if (tid == 0) {
            out[0] = sred[0] * (float)(1.0 / (32.0 * 2041.0 * 128.0));
            g_count = 0u;   // reset for next graph replay
        }
    }
}

extern "C" void kernel_launch(void* const* d_in, const int* in_sizes, int n_in,
                              void* d_out, int out_size) {
    (void)in_sizes; (void)n_in; (void)out_size;
    const float* seq = (const float*)d_in[0];
    const float* M   = (const float*)d_in[1];
    const float* A   = (const float*)d_in[2];
    const float* Bb  = (const float*)d_in[3];
    float* out = (float*)d_out;

    k_setup<<<LB + MD, MD>>>(M, A, Bb);
    k_main<<<NTILES, 256>>>(seq, out);
}